// round 4
// baseline (speedup 1.0000x reference)
#include <cuda_runtime.h>

#define N_ENTS  50000
#define N_EDGES 500000
#define RANK    128
#define SLOPE   0.22916666666666666f   // (1/8 + 1/3)/2

// ---------------- device scratch (allocation-free rule) ----------------
__device__ int   g_deg[N_ENTS];
__device__ int   g_rowptr[N_ENTS + 1];
__device__ int   g_cursor[N_ENTS];
__device__ int   g_colsrc[N_EDGES];
__device__ int   g_colet[N_EDGES];
__device__ float g_aggn[(size_t)N_ENTS * RANK];
__device__ float g_h1[(size_t)N_ENTS * RANK];
__device__ int   g_deg0_list[N_ENTS];
__device__ int   g_deg0_count;

// ---------------- small helpers ----------------
__device__ __forceinline__ unsigned long long dupf(float a) {
    unsigned long long r;
    asm("mov.b64 %0, {%1, %1};" : "=l"(r) : "f"(a));
    return r;
}
__device__ __forceinline__ void ffma2(unsigned long long& c, unsigned long long a,
                                      unsigned long long b) {
    asm("fma.rn.f32x2 %0, %1, %2, %0;" : "+l"(c) : "l"(a), "l"(b));
}

// ---------------- CSR build ----------------
__global__ void init_kernel() {
    int i = blockIdx.x * blockDim.x + threadIdx.x;
    if (i < N_ENTS) g_deg[i] = 0;
    if (i == 0) g_deg0_count = 0;
}

__global__ void hist_kernel(const int* __restrict__ dst) {
    int e = blockIdx.x * blockDim.x + threadIdx.x;
    if (e < N_EDGES) atomicAdd(&g_deg[dst[e]], 1);
}

// single block, 1024 threads: exclusive scan of degrees -> rowptr/cursor,
// collect deg-0 nodes.
__global__ void scan_kernel() {
    __shared__ int sums[1024];
    const int CH = 49;  // 1024*49 >= 50000
    int t = threadIdx.x;
    int start = t * CH;
    int end = start + CH; if (end > N_ENTS) end = N_ENTS;
    int s = 0;
    for (int i = start; i < end; i++) s += g_deg[i];
    sums[t] = s;
    __syncthreads();
    for (int off = 1; off < 1024; off <<= 1) {
        int v = (t >= off) ? sums[t - off] : 0;
        __syncthreads();
        sums[t] += v;
        __syncthreads();
    }
    int run = sums[t] - s;  // exclusive prefix
    for (int i = start; i < end; i++) {
        g_rowptr[i] = run;
        g_cursor[i] = run;
        int d = g_deg[i];
        if (d == 0) {
            int p = atomicAdd(&g_deg0_count, 1);
            g_deg0_list[p] = i;
        }
        run += d;
    }
    if (t == 1023) g_rowptr[N_ENTS] = sums[1023];
}

__global__ void fill_kernel(const int* __restrict__ src, const int* __restrict__ dst,
                            const int* __restrict__ et) {
    int e = blockIdx.x * blockDim.x + threadIdx.x;
    if (e < N_EDGES) {
        int d = dst[e];
        int p = atomicAdd(&g_cursor[d], 1);
        g_colsrc[p] = src[e];
        g_colet[p]  = et[e];
    }
}

// ---------------- aggregation (rel gather folded in, MLP-unrolled) -------
// aggn[v] = norm[v] * sum_{e into v} (h[src[e]] + rel_emb[etype[e]])
__global__ void agg_kernel(const float* __restrict__ h_ext,
                           const float* __restrict__ rel,
                           const float* __restrict__ norm) {
    const float* __restrict__ h = h_ext ? h_ext : (const float*)g_h1;
    int w = (blockIdx.x * blockDim.x + threadIdx.x) >> 5;
    if (w >= N_ENTS) return;
    int lane = threadIdx.x & 31;
    int e0 = g_rowptr[w], e1 = g_rowptr[w + 1];

    float4 acc = make_float4(0.f, 0.f, 0.f, 0.f);
    for (int base = e0; base < e1; base += 32) {
        int mys = 0, myt = 0;
        if (base + lane < e1) { mys = g_colsrc[base + lane]; myt = g_colet[base + lane]; }
        int cnt = e1 - base; if (cnt > 32) cnt = 32;
        int j = 0;
        // 4-edge unrolled body: 8 independent float4 loads in flight
        for (; j + 4 <= cnt; j += 4) {
            int s0 = __shfl_sync(0xffffffffu, mys, j);
            int s1 = __shfl_sync(0xffffffffu, mys, j + 1);
            int s2 = __shfl_sync(0xffffffffu, mys, j + 2);
            int s3 = __shfl_sync(0xffffffffu, mys, j + 3);
            int t0 = __shfl_sync(0xffffffffu, myt, j);
            int t1 = __shfl_sync(0xffffffffu, myt, j + 1);
            int t2 = __shfl_sync(0xffffffffu, myt, j + 2);
            int t3 = __shfl_sync(0xffffffffu, myt, j + 3);
            float4 a0 = reinterpret_cast<const float4*>(h + (size_t)s0 * RANK)[lane];
            float4 a1 = reinterpret_cast<const float4*>(h + (size_t)s1 * RANK)[lane];
            float4 a2 = reinterpret_cast<const float4*>(h + (size_t)s2 * RANK)[lane];
            float4 a3 = reinterpret_cast<const float4*>(h + (size_t)s3 * RANK)[lane];
            float4 r0 = reinterpret_cast<const float4*>(rel + (size_t)t0 * RANK)[lane];
            float4 r1 = reinterpret_cast<const float4*>(rel + (size_t)t1 * RANK)[lane];
            float4 r2 = reinterpret_cast<const float4*>(rel + (size_t)t2 * RANK)[lane];
            float4 r3 = reinterpret_cast<const float4*>(rel + (size_t)t3 * RANK)[lane];
            acc.x += (a0.x + r0.x) + (a1.x + r1.x) + (a2.x + r2.x) + (a3.x + r3.x);
            acc.y += (a0.y + r0.y) + (a1.y + r1.y) + (a2.y + r2.y) + (a3.y + r3.y);
            acc.z += (a0.z + r0.z) + (a1.z + r1.z) + (a2.z + r2.z) + (a3.z + r3.z);
            acc.w += (a0.w + r0.w) + (a1.w + r1.w) + (a2.w + r2.w) + (a3.w + r3.w);
        }
        for (; j < cnt; j++) {
            int s = __shfl_sync(0xffffffffu, mys, j);
            int t = __shfl_sync(0xffffffffu, myt, j);
            float4 a = reinterpret_cast<const float4*>(h + (size_t)s * RANK)[lane];
            float4 r = reinterpret_cast<const float4*>(rel + (size_t)t * RANK)[lane];
            acc.x += a.x + r.x; acc.y += a.y + r.y;
            acc.z += a.z + r.z; acc.w += a.w + r.w;
        }
    }
    float nm = norm[w];
    acc.x *= nm; acc.y *= nm; acc.z *= nm; acc.w *= nm;
    reinterpret_cast<float4*>(g_aggn + (size_t)w * RANK)[lane] = acc;
}

// Out = leaky( aggn @ Wn + h @ Wl ), fused K=256 GEMM with f32x2 packed FMA.
// BM=128, BN=128, BK=8, 256 threads, 8x8 micro-tile per thread.
__global__ void __launch_bounds__(256, 2)
gemm_kernel(const float* __restrict__ A1_ext,  // h; null -> g_h1
            const float* __restrict__ B0,      // Wn[l]
            const float* __restrict__ B1,      // Wl[l]
            float* __restrict__ out_ext)       // null -> g_h1
{
    const float* __restrict__ A0 = (const float*)g_aggn;
    const float* __restrict__ A1 = A1_ext ? A1_ext : (const float*)g_h1;
    float* __restrict__ Out = out_ext ? out_ext : (float*)g_h1;

    __shared__ float As[8][132];   // [k][m], padded stride
    __shared__ float Bs[8][128];   // [k][n]

    const int tid = threadIdx.x;
    const int block_row = blockIdx.x * 128;
    const int tx = tid & 15;       // col group: cols tx*8 .. +7
    const int ty = tid >> 4;       // row group: rows ty*8 .. +7

    unsigned long long c[8][4];
#pragma unroll
    for (int i = 0; i < 8; i++)
#pragma unroll
        for (int j = 0; j < 4; j++) c[i][j] = 0ULL;

    const int a_row  = tid >> 1;
    const int a_part = (tid & 1) * 4;
    const int b_krow = tid >> 5;
    const int b_col  = (tid & 31) * 4;
    const int grow_a = block_row + a_row;

    for (int kt = 0; kt < 32; kt++) {
        const float* Asrc = (kt < 16) ? A0 : A1;
        const float* Bsrc = (kt < 16) ? B0 : B1;
        const int kk = (kt & 15) * 8;

        float4 av = make_float4(0.f, 0.f, 0.f, 0.f);
        if (grow_a < N_ENTS)
            av = *reinterpret_cast<const float4*>(Asrc + (size_t)grow_a * RANK + kk + a_part);
        float4 bv = *reinterpret_cast<const float4*>(Bsrc + (size_t)(kk + b_krow) * RANK + b_col);

        __syncthreads();
        As[a_part + 0][a_row] = av.x;
        As[a_part + 1][a_row] = av.y;
        As[a_part + 2][a_row] = av.z;
        As[a_part + 3][a_row] = av.w;
        *reinterpret_cast<float4*>(&Bs[b_krow][b_col]) = bv;
        __syncthreads();

#pragma unroll
        for (int k2 = 0; k2 < 8; k2++) {
            float4 a0 = *reinterpret_cast<const float4*>(&As[k2][ty * 8]);
            float4 a1 = *reinterpret_cast<const float4*>(&As[k2][ty * 8 + 4]);
            const unsigned long long* bp =
                reinterpret_cast<const unsigned long long*>(&Bs[k2][tx * 8]);
            unsigned long long b0 = bp[0], b1 = bp[1], b2 = bp[2], b3 = bp[3];
            float a[8] = {a0.x, a0.y, a0.z, a0.w, a1.x, a1.y, a1.z, a1.w};
#pragma unroll
            for (int i = 0; i < 8; i++) {
                unsigned long long aa = dupf(a[i]);
                ffma2(c[i][0], aa, b0);
                ffma2(c[i][1], aa, b1);
                ffma2(c[i][2], aa, b2);
                ffma2(c[i][3], aa, b3);
            }
        }
    }

#pragma unroll
    for (int i = 0; i < 8; i++) {
        int grow = block_row + ty * 8 + i;
        if (grow >= N_ENTS) continue;
        float o[8];
#pragma unroll
        for (int j = 0; j < 4; j++) {
            float2 p = *reinterpret_cast<float2*>(&c[i][j]);
            o[2 * j] = p.x; o[2 * j + 1] = p.y;
        }
#pragma unroll
        for (int j = 0; j < 8; j++) o[j] = (o[j] >= 0.f) ? o[j] : o[j] * SLOPE;
        float* dstp = Out + (size_t)grow * RANK + tx * 8;
        *reinterpret_cast<float4*>(dstp)     = make_float4(o[0], o[1], o[2], o[3]);
        *reinterpret_cast<float4*>(dstp + 4) = make_float4(o[4], o[5], o[6], o[7]);
    }
}

// deg-0 nodes use Wa instead of Wl (and have zero agg): overwrite.
__global__ void fixup_kernel(const float* __restrict__ h_ext,
                             const float* __restrict__ Wa,
                             float* __restrict__ out_ext) {
    const float* __restrict__ h = h_ext ? h_ext : (const float*)g_h1;
    float* __restrict__ Out = out_ext ? out_ext : (float*)g_h1;
    int wg = (blockIdx.x * blockDim.x + threadIdx.x) >> 5;
    int lane = threadIdx.x & 31;
    int nwarp = (gridDim.x * blockDim.x) >> 5;
    int cnt = g_deg0_count;
    for (int idx = wg; idx < cnt; idx += nwarp) {
        int v = g_deg0_list[idx];
        const float* hr = h + (size_t)v * RANK;
        float4 acc = make_float4(0.f, 0.f, 0.f, 0.f);
        for (int k = 0; k < RANK; k++) {
            float a = hr[k];
            float4 wv = reinterpret_cast<const float4*>(Wa + (size_t)k * RANK)[lane];
            acc.x += a * wv.x; acc.y += a * wv.y; acc.z += a * wv.z; acc.w += a * wv.w;
        }
        acc.x = (acc.x >= 0.f) ? acc.x : acc.x * SLOPE;
        acc.y = (acc.y >= 0.f) ? acc.y : acc.y * SLOPE;
        acc.z = (acc.z >= 0.f) ? acc.z : acc.z * SLOPE;
        acc.w = (acc.w >= 0.f) ? acc.w : acc.w * SLOPE;
        reinterpret_cast<float4*>(Out + (size_t)v * RANK)[lane] = acc;
    }
}

// ---------------- launch ----------------
extern "C" void kernel_launch(void* const* d_in, const int* in_sizes, int n_in,
                              void* d_out, int out_size) {
    const float* ent  = (const float*)d_in[0];
    const float* rel  = (const float*)d_in[1];
    const float* norm = (const float*)d_in[2];
    const float* Wn   = (const float*)d_in[3];
    const float* Wl   = (const float*)d_in[4];
    const float* Wa   = (const float*)d_in[5];
    const int*   src  = (const int*)d_in[6];
    const int*   dst  = (const int*)d_in[7];
    const int*   et   = (const int*)d_in[8];
    float* out = (float*)d_out;

    const int NB  = (N_ENTS + 255) / 256;
    const int EB  = (N_EDGES + 255) / 256;
    const int AGB = (N_ENTS * 32 + 255) / 256;   // warp-per-node
    const int GB  = (N_ENTS + 127) / 128;

    init_kernel<<<NB, 256>>>();
    hist_kernel<<<EB, 256>>>(dst);
    scan_kernel<<<1, 1024>>>();
    fill_kernel<<<EB, 256>>>(src, dst, et);

    const int WSTRIDE = RANK * RANK;  // 16384

    // layer 0: h_in = ent_emb, h_out = g_h1
    agg_kernel<<<AGB, 256>>>(ent, rel, norm);
    gemm_kernel<<<GB, 256>>>(ent, Wn + 0 * WSTRIDE, Wl + 0 * WSTRIDE, nullptr);
    fixup_kernel<<<8, 256>>>(ent, Wa + 0 * WSTRIDE, nullptr);

    // layer 1: h_in = g_h1, h_out = d_out
    agg_kernel<<<AGB, 256>>>(nullptr, norm ? rel : rel, norm);
    gemm_kernel<<<GB, 256>>>(nullptr, Wn + 1 * WSTRIDE, Wl + 1 * WSTRIDE, out);
    fixup_kernel<<<8, 256>>>(nullptr, Wa + 1 * WSTRIDE, out);
}

// round 5
// speedup vs baseline: 1.1572x; 1.1572x over previous
#include <cuda_runtime.h>
#include <cuda_bf16.h>

#define N_ENTS  50000
#define N_EDGES 500000
#define RANK    128
#define SLOPE   0.22916666666666666f   // (1/8 + 1/3)/2

typedef unsigned int u32;

// ---------------- device scratch (allocation-free rule) ----------------
__device__ int   g_deg[N_ENTS];
__device__ int   g_rowptr[N_ENTS + 1];
__device__ int   g_cursor[N_ENTS];
__device__ int   g_colsrc[N_EDGES];
__device__ int   g_colet[N_EDGES];
__device__ float g_h1[(size_t)N_ENTS * RANK];
__device__ float g_sumrel[(size_t)N_ENTS * RANK];
// A' bf16 [N_ENTS][256]: cols 0-127 = scaled agg, cols 128-255 = h
__device__ __nv_bfloat16 g_Ahi[(size_t)N_ENTS * 256];
__device__ __nv_bfloat16 g_Alo[(size_t)N_ENTS * 256];
// W' bf16 [layer][region hi/lo][n=128][k=256] (k contiguous; k<128: Wn, else Wl)
__device__ __nv_bfloat16 g_Wt[2 * 2 * 128 * 256];
__device__ int   g_deg0_list[N_ENTS];
__device__ int   g_deg0_count;

// ---------------- helpers ----------------
__device__ __forceinline__ u32 smem_u32(const void* p) {
    u32 a;
    asm("{ .reg .u64 t; cvta.to.shared.u64 t, %1; cvt.u32.u64 %0, t; }"
        : "=r"(a) : "l"(p));
    return a;
}
__device__ __forceinline__ void ldmx4(u32* r, u32 addr) {
    asm volatile("ldmatrix.sync.aligned.m8n8.x4.shared.b16 {%0,%1,%2,%3}, [%4];"
                 : "=r"(r[0]), "=r"(r[1]), "=r"(r[2]), "=r"(r[3]) : "r"(addr));
}
__device__ __forceinline__ void mma16816(float* c, const u32* a, const u32* b) {
    asm volatile(
        "mma.sync.aligned.m16n8k16.row.col.f32.bf16.bf16.f32 "
        "{%0,%1,%2,%3}, {%4,%5,%6,%7}, {%8,%9}, {%0,%1,%2,%3};"
        : "+f"(c[0]), "+f"(c[1]), "+f"(c[2]), "+f"(c[3])
        : "r"(a[0]), "r"(a[1]), "r"(a[2]), "r"(a[3]), "r"(b[0]), "r"(b[1]));
}
__device__ __forceinline__ void pack4(const float* v, uint2& uh, uint2& ul) {
    unsigned short hb[4], lb[4];
#pragma unroll
    for (int i = 0; i < 4; i++) {
        __nv_bfloat16 h = __float2bfloat16_rn(v[i]);
        __nv_bfloat16 l = __float2bfloat16_rn(v[i] - __bfloat162float(h));
        hb[i] = __bfloat16_as_ushort(h);
        lb[i] = __bfloat16_as_ushort(l);
    }
    uh.x = (u32)hb[0] | ((u32)hb[1] << 16);
    uh.y = (u32)hb[2] | ((u32)hb[3] << 16);
    ul.x = (u32)lb[0] | ((u32)lb[1] << 16);
    ul.y = (u32)lb[2] | ((u32)lb[3] << 16);
}

// ---------------- CSR build ----------------
__global__ void init_kernel() {
    int i = blockIdx.x * blockDim.x + threadIdx.x;
    if (i < N_ENTS) g_deg[i] = 0;
    if (i == 0) g_deg0_count = 0;
}

__global__ void hist_kernel(const int* __restrict__ dst) {
    int e = blockIdx.x * blockDim.x + threadIdx.x;
    if (e < N_EDGES) atomicAdd(&g_deg[dst[e]], 1);
}

__global__ void scan_kernel() {
    __shared__ int sums[1024];
    const int CH = 49;
    int t = threadIdx.x;
    int start = t * CH;
    int end = start + CH; if (end > N_ENTS) end = N_ENTS;
    int s = 0;
    for (int i = start; i < end; i++) s += g_deg[i];
    sums[t] = s;
    __syncthreads();
    for (int off = 1; off < 1024; off <<= 1) {
        int v = (t >= off) ? sums[t - off] : 0;
        __syncthreads();
        sums[t] += v;
        __syncthreads();
    }
    int run = sums[t] - s;
    for (int i = start; i < end; i++) {
        g_rowptr[i] = run;
        g_cursor[i] = run;
        int d = g_deg[i];
        if (d == 0) {
            int p = atomicAdd(&g_deg0_count, 1);
            g_deg0_list[p] = i;
        }
        run += d;
    }
    if (t == 1023) g_rowptr[N_ENTS] = sums[1023];
}

__global__ void fill_kernel(const int* __restrict__ src, const int* __restrict__ dst,
                            const int* __restrict__ et) {
    int e = blockIdx.x * blockDim.x + threadIdx.x;
    if (e < N_EDGES) {
        int d = dst[e];
        int p = atomicAdd(&g_cursor[d], 1);
        g_colsrc[p] = src[e];
        g_colet[p]  = et[e];
    }
}

// ---------------- weight / input conversion ----------------
__global__ void wtbuild_kernel(const float* __restrict__ Wn, const float* __restrict__ Wl) {
    int idx = blockIdx.x * blockDim.x + threadIdx.x;   // 2*2*128*256
    if (idx >= 2 * 2 * 128 * 256) return;
    int k = idx & 255;
    int n = (idx >> 8) & 127;
    int reg = (idx >> 15) & 1;
    int l = idx >> 16;
    const float* W = (k < 128) ? (Wn + l * 16384 + k * 128 + n)
                               : (Wl + l * 16384 + (k - 128) * 128 + n);
    float v = *W;
    __nv_bfloat16 hi = __float2bfloat16_rn(v);
    __nv_bfloat16 o = reg ? __float2bfloat16_rn(v - __bfloat162float(hi)) : hi;
    g_Wt[idx] = o;
}

__global__ void entconv_kernel(const float* __restrict__ ent) {
    int idx = blockIdx.x * blockDim.x + threadIdx.x;   // N_ENTS*32
    if (idx >= N_ENTS * 32) return;
    int row = idx >> 5, q = idx & 31;
    float4 v = reinterpret_cast<const float4*>(ent + (size_t)row * RANK)[q];
    float f[4] = {v.x, v.y, v.z, v.w};
    uint2 uh, ul;
    pack4(f, uh, ul);
    *reinterpret_cast<uint2*>(g_Ahi + (size_t)row * 256 + 128 + q * 4) = uh;
    *reinterpret_cast<uint2*>(g_Alo + (size_t)row * 256 + 128 + q * 4) = ul;
}

// ---------------- aggregation ----------------
// mode 0: gather h+rel, store sumrel, write bf16 agg (cols 0-127)
// mode 1: gather h only, add stored sumrel
__global__ void agg_kernel(const float* __restrict__ h_ext,
                           const float* __restrict__ rel,
                           const float* __restrict__ norm, int mode) {
    const float* __restrict__ h = h_ext ? h_ext : (const float*)g_h1;
    int w = (blockIdx.x * blockDim.x + threadIdx.x) >> 5;
    if (w >= N_ENTS) return;
    int lane = threadIdx.x & 31;
    int e0 = g_rowptr[w], e1 = g_rowptr[w + 1];

    float4 acc = make_float4(0.f, 0.f, 0.f, 0.f);
    float4 racc = make_float4(0.f, 0.f, 0.f, 0.f);
    for (int base = e0; base < e1; base += 32) {
        int mys = 0, myt = 0;
        if (base + lane < e1) { mys = g_colsrc[base + lane]; myt = g_colet[base + lane]; }
        int cnt = e1 - base; if (cnt > 32) cnt = 32;
        int j = 0;
        for (; j + 2 <= cnt; j += 2) {
            int s0 = __shfl_sync(0xffffffffu, mys, j);
            int s1 = __shfl_sync(0xffffffffu, mys, j + 1);
            float4 a0 = reinterpret_cast<const float4*>(h + (size_t)s0 * RANK)[lane];
            float4 a1 = reinterpret_cast<const float4*>(h + (size_t)s1 * RANK)[lane];
            acc.x += a0.x + a1.x; acc.y += a0.y + a1.y;
            acc.z += a0.z + a1.z; acc.w += a0.w + a1.w;
            if (mode == 0) {
                int t0 = __shfl_sync(0xffffffffu, myt, j);
                int t1 = __shfl_sync(0xffffffffu, myt, j + 1);
                float4 r0 = reinterpret_cast<const float4*>(rel + (size_t)t0 * RANK)[lane];
                float4 r1 = reinterpret_cast<const float4*>(rel + (size_t)t1 * RANK)[lane];
                racc.x += r0.x + r1.x; racc.y += r0.y + r1.y;
                racc.z += r0.z + r1.z; racc.w += r0.w + r1.w;
            }
        }
        for (; j < cnt; j++) {
            int s = __shfl_sync(0xffffffffu, mys, j);
            float4 a = reinterpret_cast<const float4*>(h + (size_t)s * RANK)[lane];
            acc.x += a.x; acc.y += a.y; acc.z += a.z; acc.w += a.w;
            if (mode == 0) {
                int t = __shfl_sync(0xffffffffu, myt, j);
                float4 r = reinterpret_cast<const float4*>(rel + (size_t)t * RANK)[lane];
                racc.x += r.x; racc.y += r.y; racc.z += r.z; racc.w += r.w;
            }
        }
    }
    if (mode == 0) {
        reinterpret_cast<float4*>(g_sumrel + (size_t)w * RANK)[lane] = racc;
    } else {
        racc = reinterpret_cast<const float4*>(g_sumrel + (size_t)w * RANK)[lane];
    }
    float nm = norm[w];
    float f[4] = {(acc.x + racc.x) * nm, (acc.y + racc.y) * nm,
                  (acc.z + racc.z) * nm, (acc.w + racc.w) * nm};
    uint2 uh, ul;
    pack4(f, uh, ul);
    *reinterpret_cast<uint2*>(g_Ahi + (size_t)w * 256 + lane * 4) = uh;
    *reinterpret_cast<uint2*>(g_Alo + (size_t)w * 256 + lane * 4) = ul;
}

// ---------------- bf16-split mma.sync GEMM ----------------
// D[128 rows/block][128] = sum over 3 passes (Ahi*Whi, Ahi*Wlo, Alo*Whi), K=256 each.
// 256 threads = 8 warps (4 m x 2 n). Warp tile 32x64. fp32 accum.
__global__ void __launch_bounds__(256, 2)
gemm_kernel(int layer, float* __restrict__ out_ext, int write_bf16) {
    float* __restrict__ outf = out_ext ? out_ext : (float*)g_h1;

    __shared__ __align__(16) char sA[128 * 144];   // [row][64 bf16 +8 pad]
    __shared__ __align__(16) char sB[128 * 144];   // [n][64 bf16 +8 pad]

    const int tid = threadIdx.x;
    const int lane = tid & 31;
    const int wid = tid >> 5;
    const int warp_m = wid & 3;     // 0..3 -> rows 32*warp_m
    const int warp_n = wid >> 2;    // 0..1 -> cols 64*warp_n
    const int block_row = blockIdx.x * 128;

    const u32 sAu = smem_u32(sA);
    const u32 sBu = smem_u32(sB);

    // ldmatrix per-lane addressing
    const int a_q = lane >> 3;
    const int a_row = (lane & 7) + (a_q & 1) * 8;       // within m16 tile
    const int a_kb = (a_q >> 1) * 16;                    // k-half bytes
    const int b_q = lane >> 3;
    const int b_row = ((b_q >> 1) * 8) + (lane & 7);     // within n16 pair
    const int b_kb = (b_q & 1) * 16;

    float c[2][8][4];
#pragma unroll
    for (int t = 0; t < 2; t++)
#pragma unroll
        for (int n = 0; n < 8; n++)
#pragma unroll
            for (int r = 0; r < 4; r++) c[t][n][r] = 0.f;

    for (int kc = 0; kc < 12; kc++) {
        const int pass = kc >> 2;
        const __nv_bfloat16* __restrict__ Asrc = (pass < 2) ? g_Ahi : g_Alo;
        const int region = (pass == 1) ? 1 : 0;
        const __nv_bfloat16* __restrict__ Bsrc =
            g_Wt + ((size_t)(layer * 2 + region) << 15);
        const int kcol = (kc & 3) * 64;

        __syncthreads();
#pragma unroll
        for (int i = 0; i < 4; i++) {
            int idx = tid + i * 256;       // 0..1023
            int row = idx >> 3;
            int grp = (idx & 7) * 16;      // byte group
            uint4 va = make_uint4(0u, 0u, 0u, 0u);
            int grow = block_row + row;
            if (grow < N_ENTS)
                va = *reinterpret_cast<const uint4*>(
                    reinterpret_cast<const char*>(Asrc + (size_t)grow * 256 + kcol) + grp);
            *reinterpret_cast<uint4*>(sA + row * 144 + grp) = va;
            uint4 vb = *reinterpret_cast<const uint4*>(
                reinterpret_cast<const char*>(Bsrc + (size_t)row * 256 + kcol) + grp);
            *reinterpret_cast<uint4*>(sB + row * 144 + grp) = vb;
        }
        __syncthreads();

#pragma unroll
        for (int j = 0; j < 4; j++) {
            u32 aa[2][4];
#pragma unroll
            for (int t = 0; t < 2; t++) {
                u32 addr = sAu + (warp_m * 32 + t * 16 + a_row) * 144 + j * 32 + a_kb;
                ldmx4(aa[t], addr);
            }
#pragma unroll
            for (int p = 0; p < 4; p++) {
                u32 bb[4];
                u32 addr = sBu + (warp_n * 64 + p * 16 + b_row) * 144 + j * 32 + b_kb;
                ldmx4(bb, addr);
#pragma unroll
                for (int t = 0; t < 2; t++) {
                    mma16816(c[t][2 * p],     aa[t], bb);
                    mma16816(c[t][2 * p + 1], aa[t], bb + 2);
                }
            }
        }
    }

    // epilogue: leaky relu, write fp32 (+ bf16 hi/lo h-part for next layer)
    const int er = lane >> 2;            // 0..7
    const int ec = (lane & 3) * 2;       // 0,2,4,6
#pragma unroll
    for (int t = 0; t < 2; t++) {
#pragma unroll
        for (int half = 0; half < 2; half++) {
            int grow = block_row + warp_m * 32 + t * 16 + er + half * 8;
            if (grow >= N_ENTS) continue;
#pragma unroll
            for (int n = 0; n < 8; n++) {
                int col = warp_n * 64 + n * 8 + ec;
                float v0 = c[t][n][half * 2 + 0];
                float v1 = c[t][n][half * 2 + 1];
                v0 = (v0 >= 0.f) ? v0 : v0 * SLOPE;
                v1 = (v1 >= 0.f) ? v1 : v1 * SLOPE;
                *reinterpret_cast<float2*>(outf + (size_t)grow * RANK + col) =
                    make_float2(v0, v1);
                if (write_bf16) {
                    __nv_bfloat16 h0 = __float2bfloat16_rn(v0);
                    __nv_bfloat16 h1 = __float2bfloat16_rn(v1);
                    __nv_bfloat16 l0 = __float2bfloat16_rn(v0 - __bfloat162float(h0));
                    __nv_bfloat16 l1 = __float2bfloat16_rn(v1 - __bfloat162float(h1));
                    u32 ph = (u32)__bfloat16_as_ushort(h0) |
                             ((u32)__bfloat16_as_ushort(h1) << 16);
                    u32 pl = (u32)__bfloat16_as_ushort(l0) |
                             ((u32)__bfloat16_as_ushort(l1) << 16);
                    *reinterpret_cast<u32*>(g_Ahi + (size_t)grow * 256 + 128 + col) = ph;
                    *reinterpret_cast<u32*>(g_Alo + (size_t)grow * 256 + 128 + col) = pl;
                }
            }
        }
    }
}

// ---------------- deg-0 fixup ----------------
__global__ void fixup_kernel(const float* __restrict__ h_ext,
                             const float* __restrict__ Wa,
                             float* __restrict__ out_ext, int write_bf16) {
    const float* __restrict__ h = h_ext ? h_ext : (const float*)g_h1;
    float* __restrict__ Out = out_ext ? out_ext : (float*)g_h1;
    int wg = (blockIdx.x * blockDim.x + threadIdx.x) >> 5;
    int lane = threadIdx.x & 31;
    int nwarp = (gridDim.x * blockDim.x) >> 5;
    int cnt = g_deg0_count;
    for (int idx = wg; idx < cnt; idx += nwarp) {
        int v = g_deg0_list[idx];
        const float* hr = h + (size_t)v * RANK;
        float4 acc = make_float4(0.f, 0.f, 0.f, 0.f);
        for (int k = 0; k < RANK; k++) {
            float a = hr[k];
            float4 wv = reinterpret_cast<const float4*>(Wa + (size_t)k * RANK)[lane];
            acc.x += a * wv.x; acc.y += a * wv.y;
            acc.z += a * wv.z; acc.w += a * wv.w;
        }
        float f[4];
        f[0] = (acc.x >= 0.f) ? acc.x : acc.x * SLOPE;
        f[1] = (acc.y >= 0.f) ? acc.y : acc.y * SLOPE;
        f[2] = (acc.z >= 0.f) ? acc.z : acc.z * SLOPE;
        f[3] = (acc.w >= 0.f) ? acc.w : acc.w * SLOPE;
        reinterpret_cast<float4*>(Out + (size_t)v * RANK)[lane] =
            make_float4(f[0], f[1], f[2], f[3]);
        if (write_bf16) {
            uint2 uh, ul;
            pack4(f, uh, ul);
            *reinterpret_cast<uint2*>(g_Ahi + (size_t)v * 256 + 128 + lane * 4) = uh;
            *reinterpret_cast<uint2*>(g_Alo + (size_t)v * 256 + 128 + lane * 4) = ul;
        }
    }
}

// ---------------- launch ----------------
extern "C" void kernel_launch(void* const* d_in, const int* in_sizes, int n_in,
                              void* d_out, int out_size) {
    const float* ent  = (const float*)d_in[0];
    const float* rel  = (const float*)d_in[1];
    const float* norm = (const float*)d_in[2];
    const float* Wn   = (const float*)d_in[3];
    const float* Wl   = (const float*)d_in[4];
    const float* Wa   = (const float*)d_in[5];
    const int*   src  = (const int*)d_in[6];
    const int*   dst  = (const int*)d_in[7];
    const int*   et   = (const int*)d_in[8];
    float* out = (float*)d_out;

    const int NB  = (N_ENTS + 255) / 256;
    const int EB  = (N_EDGES + 255) / 256;
    const int AGB = (N_ENTS * 32 + 255) / 256;
    const int GB  = (N_ENTS + 127) / 128;

    // prep (independent of CSR)
    wtbuild_kernel<<<(2 * 2 * 128 * 256 + 255) / 256, 256>>>(Wn, Wl);
    entconv_kernel<<<(N_ENTS * 32 + 255) / 256, 256>>>(ent);

    // CSR build
    init_kernel<<<NB, 256>>>();
    hist_kernel<<<EB, 256>>>(dst);
    scan_kernel<<<1, 1024>>>();
    fill_kernel<<<EB, 256>>>(src, dst, et);

    const int WSTRIDE = RANK * RANK;

    // layer 0
    agg_kernel<<<AGB, 256>>>(ent, rel, norm, 0);
    gemm_kernel<<<GB, 256>>>(0, nullptr, 1);
    fixup_kernel<<<8, 256>>>(ent, Wa + 0 * WSTRIDE, nullptr, 1);

    // layer 1
    agg_kernel<<<AGB, 256>>>(nullptr, rel, norm, 1);
    gemm_kernel<<<GB, 256>>>(1, out, 0);
    fixup_kernel<<<8, 256>>>(nullptr, Wa + 1 * WSTRIDE, out, 0);
}